// round 2
// baseline (speedup 1.0000x reference)
#include <cuda_runtime.h>
#include <cstdint>
#include <math.h>

// ---------------- problem constants ----------------
#define T_STEPS 512
#define BATCH   64
#define EMB_D   400
#define HID_D   1152
#define M_ROWS  (T_STEPS * BATCH)   // 32768

// ---------------- scratch (static device memory; no cudaMalloc allowed) ----
__device__ float g_act0[(size_t)M_ROWS * HID_D];        // 151 MB
__device__ float g_act1[(size_t)M_ROWS * HID_D];        // 151 MB
__device__ float g_xw[(size_t)M_ROWS * 4 * HID_D];      // 604 MB
__device__ float g_h[2][BATCH * HID_D];                 // double-buffered hidden state
__device__ unsigned int g_arrive;                       // grid barrier counter

// ---------------- packed f32x2 helpers (numerically identical to scalar fmaf) --
__device__ __forceinline__ unsigned long long pack2(float lo, float hi) {
    unsigned long long r;
    asm("mov.b64 %0, {%1, %2};" : "=l"(r) : "f"(lo), "f"(hi));
    return r;
}
__device__ __forceinline__ void unpack2(unsigned long long v, float& lo, float& hi) {
    asm("mov.b64 {%0, %1}, %2;" : "=f"(lo), "=f"(hi) : "l"(v));
}
__device__ __forceinline__ unsigned long long fma2(unsigned long long a,
                                                   unsigned long long b,
                                                   unsigned long long c) {
    unsigned long long d;
    asm("fma.rn.f32x2 %0, %1, %2, %3;" : "=l"(d) : "l"(a), "l"(b), "l"(c));
    return d;
}

// ---------------- helpers ----------------
__device__ __forceinline__ float sigm(float x) { return 1.0f / (1.0f + expf(-x)); }

__device__ __forceinline__ void grid_barrier(int nctas, unsigned int target) {
    __syncthreads();
    if (threadIdx.x == 0) {
        __threadfence();
        atomicAdd(&g_arrive, 1u);
        unsigned int v;
        while (true) {
            asm volatile("ld.acquire.gpu.u32 %0, [%1];" : "=r"(v) : "l"(&g_arrive) : "memory");
            if (v >= target) break;
            __nanosleep(128);
        }
    }
    __syncthreads();
}

__global__ void reset_bar_kernel() { g_arrive = 0u; }

// ---------------- embedding gather ----------------
__global__ void embed_kernel(const int* __restrict__ x, const float* __restrict__ emb,
                             float* __restrict__ out) {
    const int m = blockIdx.x;                 // 0 .. T*B-1
    const int tok = x[m];
    const float4* src = (const float4*)(emb + (size_t)tok * EMB_D);
    float4* dst = (float4*)(out + (size_t)m * EMB_D);
    for (int i = threadIdx.x; i < EMB_D / 4; i += blockDim.x) dst[i] = src[i];
}

// ---------------- input projection: out[M][N] = A[M][K] @ W[N][K]^T + (bih+bhh) ----
// 128x128 tile, BK=8, 256 threads, 8x8 per-thread micro-tile, FFMA2 inner loop.
__global__ void __launch_bounds__(256)
gemm_xw_kernel(const float* __restrict__ A, const float* __restrict__ W,
               const float* __restrict__ bih, const float* __restrict__ bhh,
               float* __restrict__ out, int N, int K) {
    __shared__ float sA[8][128];
    __shared__ float sB[8][128];
    const int tid = threadIdx.x;
    const int tx = tid & 15;    // n sub-tile
    const int ty = tid >> 4;    // m sub-tile
    const int m0 = blockIdx.y * 128;
    const int n0 = blockIdx.x * 128;

    const int lrow = tid >> 1;          // 0..127
    const int lkq  = (tid & 1) * 4;     // 0 or 4
    const float* Ap = A + (size_t)(m0 + lrow) * K + lkq;
    const int nrow = n0 + lrow;
    const float* Wp = W + (size_t)nrow * K + lkq;
    const bool wok = (nrow < N);

    unsigned long long acc2[8][4];      // [m][n-pair], each holds 2 packed f32
#pragma unroll
    for (int i = 0; i < 8; ++i)
#pragma unroll
        for (int jp = 0; jp < 4; ++jp) acc2[i][jp] = 0ull;

    for (int kt = 0; kt < K; kt += 8) {
        float4 av = *(const float4*)(Ap + kt);
        float4 wv = wok ? *(const float4*)(Wp + kt) : make_float4(0.f, 0.f, 0.f, 0.f);
        sA[lkq + 0][lrow] = av.x; sA[lkq + 1][lrow] = av.y;
        sA[lkq + 2][lrow] = av.z; sA[lkq + 3][lrow] = av.w;
        sB[lkq + 0][lrow] = wv.x; sB[lkq + 1][lrow] = wv.y;
        sB[lkq + 2][lrow] = wv.z; sB[lkq + 3][lrow] = wv.w;
        __syncthreads();
#pragma unroll
        for (int k = 0; k < 8; ++k) {
            float ra[8];
            *(float4*)&ra[0] = *(const float4*)&sA[k][ty * 8];
            *(float4*)&ra[4] = *(const float4*)&sA[k][ty * 8 + 4];
            // B fragment comes packed for free: 8 consecutive floats = 4 f32x2 pairs
            ulonglong2 rb01 = *(const ulonglong2*)&sB[k][tx * 8];
            ulonglong2 rb23 = *(const ulonglong2*)&sB[k][tx * 8 + 4];
            unsigned long long rb2[4] = {rb01.x, rb01.y, rb23.x, rb23.y};
#pragma unroll
            for (int i = 0; i < 8; ++i) {
                const unsigned long long ai = pack2(ra[i], ra[i]);
#pragma unroll
                for (int jp = 0; jp < 4; ++jp)
                    acc2[i][jp] = fma2(ai, rb2[jp], acc2[i][jp]);
            }
        }
        __syncthreads();
    }

    float bias[8];
#pragma unroll
    for (int j = 0; j < 8; ++j) {
        const int n = n0 + tx * 8 + j;
        bias[j] = (n < N) ? (__ldg(bih + n) + __ldg(bhh + n)) : 0.0f;
    }
#pragma unroll
    for (int i = 0; i < 8; ++i) {
        float vals[8];
#pragma unroll
        for (int jp = 0; jp < 4; ++jp) unpack2(acc2[i][jp], vals[2 * jp], vals[2 * jp + 1]);
        float* orow = out + (size_t)(m0 + ty * 8 + i) * N + n0 + tx * 8;
#pragma unroll
        for (int j = 0; j < 8; ++j)
            if (n0 + tx * 8 + j < N) orow[j] = vals[j] + bias[j];
    }
}

// ---------------- persistent recurrent LSTM layer ----------------
// H hidden units, NJ units per CTA (grid = H/NJ CTAs, all resident).
// SMEM: W_hh slice [4*NJ][H+5], h stage [32][64], gate exchange [64][4*NJ], cell [64][NJ].
template <int H, int NJ>
__global__ void __launch_bounds__(256, 1)
lstm_rec_kernel(const float* __restrict__ xw, const float* __restrict__ Whh,
                float* __restrict__ out, int nctas) {
    constexpr int FOUR_NJ = 4 * NJ;
    constexpr int WS = H + 5;               // pad -> conflict-free row access
    constexpr int RPT = FOUR_NJ / 16;       // gate-rows per thread (2 or 1)

    extern __shared__ float sm[];
    float* sW    = sm;                          // [FOUR_NJ][WS]
    float* sA    = sW + FOUR_NJ * WS;           // [32][64] k-major h stage
    float* sC    = sA + 32 * 64;                // [64][FOUR_NJ]
    float* sCell = sC + 64 * FOUR_NJ;           // [64][NJ]

    const int tid = threadIdx.x;
    const int j0  = blockIdx.x * NJ;
    const int rx  = tid & 15;       // gate-row group
    const int bx  = tid >> 4;       // batch quad

    // cache W_hh slice in SMEM (rows: g*NJ+u  <->  global row g*H + j0 + u)
    for (int r = 0; r < FOUR_NJ; ++r) {
        const int grow = (r / NJ) * H + j0 + (r % NJ);
        const float* wsrc = Whh + (size_t)grow * H;
        for (int k = tid * 4; k < H; k += 1024) {
            float4 v = *(const float4*)(wsrc + k);
            sW[r * WS + k + 0] = v.x; sW[r * WS + k + 1] = v.y;
            sW[r * WS + k + 2] = v.z; sW[r * WS + k + 3] = v.w;
        }
    }
    // zero cell state + h buffer 0 (this CTA's slice)
    for (int i = tid; i < BATCH * NJ; i += 256) {
        sCell[i] = 0.0f;
        const int b = i / NJ, u = i % NJ;
        g_h[0][b * H + j0 + u] = 0.0f;
    }
    unsigned int ep = 1;
    grid_barrier(nctas, ep * (unsigned)nctas); ++ep;

    for (int t = 0; t < T_STEPS; ++t) {
        const int rb = t & 1;
        const float* hbuf = g_h[rb];

        unsigned long long acc2[RPT][2];    // [row][batch-pair], packed f32x2
#pragma unroll
        for (int rp = 0; rp < RPT; ++rp) { acc2[rp][0] = 0ull; acc2[rp][1] = 0ull; }

        for (int kt = 0; kt < H; kt += 32) {
            const int chunk = (H - kt) < 32 ? (H - kt) : 32;
            __syncthreads();
            {   // stage h[0..63][kt..kt+31] transposed into sA[k][b] (.cg: skip stale L1)
                const int b = tid >> 2, kq = (tid & 3) * 8;
                float4 v0 = __ldcg((const float4*)(hbuf + b * H + kt + kq));
                float4 v1 = __ldcg((const float4*)(hbuf + b * H + kt + kq + 4));
                sA[(kq + 0) * 64 + b] = v0.x; sA[(kq + 1) * 64 + b] = v0.y;
                sA[(kq + 2) * 64 + b] = v0.z; sA[(kq + 3) * 64 + b] = v0.w;
                sA[(kq + 4) * 64 + b] = v1.x; sA[(kq + 5) * 64 + b] = v1.y;
                sA[(kq + 6) * 64 + b] = v1.z; sA[(kq + 7) * 64 + b] = v1.w;
            }
            __syncthreads();
            if (chunk == 32) {
#pragma unroll
                for (int kk = 0; kk < 32; ++kk) {
                    // 4 consecutive batch h-values = 2 packed f32x2 pairs, free
                    ulonglong2 av = *(const ulonglong2*)(sA + kk * 64 + bx * 4);
#pragma unroll
                    for (int rp = 0; rp < RPT; ++rp) {
                        const float w = sW[(rx * RPT + rp) * WS + kt + kk];
                        const unsigned long long w2 = pack2(w, w);
                        acc2[rp][0] = fma2(w2, av.x, acc2[rp][0]);
                        acc2[rp][1] = fma2(w2, av.y, acc2[rp][1]);
                    }
                }
            } else {
                for (int kk = 0; kk < chunk; ++kk) {
                    ulonglong2 av = *(const ulonglong2*)(sA + kk * 64 + bx * 4);
#pragma unroll
                    for (int rp = 0; rp < RPT; ++rp) {
                        const float w = sW[(rx * RPT + rp) * WS + kt + kk];
                        const unsigned long long w2 = pack2(w, w);
                        acc2[rp][0] = fma2(w2, av.x, acc2[rp][0]);
                        acc2[rp][1] = fma2(w2, av.y, acc2[rp][1]);
                    }
                }
            }
        }

        // add precomputed input projection, exchange gates through SMEM
        const float* xwstep = xw + (size_t)t * BATCH * (4 * H);
#pragma unroll
        for (int rp = 0; rp < RPT; ++rp) {
            const int r = rx * RPT + rp;
            const int g = r / NJ, u = r % NJ;
            float aq[4];
            unpack2(acc2[rp][0], aq[0], aq[1]);
            unpack2(acc2[rp][1], aq[2], aq[3]);
#pragma unroll
            for (int q = 0; q < 4; ++q) {
                const int b = bx * 4 + q;
                sC[b * FOUR_NJ + r] = aq[q] + xwstep[(size_t)b * 4 * H + g * H + j0 + u];
            }
        }
        __syncthreads();

        // cell/hidden update for owned units
        float* hout = g_h[1 - rb];
        for (int i = tid; i < BATCH * NJ; i += 256) {
            const int b = i / NJ, u = i % NJ;
            const float gi = sC[b * FOUR_NJ + 0 * NJ + u];
            const float gf = sC[b * FOUR_NJ + 1 * NJ + u];
            const float gg = sC[b * FOUR_NJ + 2 * NJ + u];
            const float go = sC[b * FOUR_NJ + 3 * NJ + u];
            float c = sCell[i];
            c = sigm(gf) * c + sigm(gi) * tanhf(gg);
            sCell[i] = c;
            const float hv = sigm(go) * tanhf(c);
            hout[b * H + j0 + u] = hv;
            out[((size_t)t * BATCH + b) * H + j0 + u] = hv;
        }
        grid_barrier(nctas, ep * (unsigned)nctas); ++ep;
    }
}

// ---------------- launch ----------------
extern "C" void kernel_launch(void* const* d_in, const int* in_sizes, int n_in,
                              void* d_out, int out_size) {
    (void)in_sizes; (void)n_in; (void)out_size;
    const int*   x    = (const int*)d_in[0];
    const float* emb  = (const float*)d_in[1];
    const float* Wih0 = (const float*)d_in[2];
    const float* Whh0 = (const float*)d_in[3];
    const float* bih0 = (const float*)d_in[4];
    const float* bhh0 = (const float*)d_in[5];
    const float* Wih1 = (const float*)d_in[6];
    const float* Whh1 = (const float*)d_in[7];
    const float* bih1 = (const float*)d_in[8];
    const float* bhh1 = (const float*)d_in[9];
    const float* Wih2 = (const float*)d_in[10];
    const float* Whh2 = (const float*)d_in[11];
    const float* bih2 = (const float*)d_in[12];
    const float* bhh2 = (const float*)d_in[13];
    float* out = (float*)d_out;

    float *act0, *act1, *xw;
    cudaGetSymbolAddress((void**)&act0, g_act0);
    cudaGetSymbolAddress((void**)&act1, g_act1);
    cudaGetSymbolAddress((void**)&xw, g_xw);

    const size_t SMEM_BIG   = (size_t)(32 * (HID_D + 5) + 32 * 64 + 64 * 32 + 64 * 8) * sizeof(float);
    const size_t SMEM_SMALL = (size_t)(16 * (EMB_D + 5) + 32 * 64 + 64 * 16 + 64 * 4) * sizeof(float);
    cudaFuncSetAttribute((const void*)lstm_rec_kernel<HID_D, 8>,
                         cudaFuncAttributeMaxDynamicSharedMemorySize, (int)SMEM_BIG);
    cudaFuncSetAttribute((const void*)lstm_rec_kernel<EMB_D, 4>,
                         cudaFuncAttributeMaxDynamicSharedMemorySize, (int)SMEM_SMALL);

    // embedding
    embed_kernel<<<M_ROWS, 128>>>(x, emb, act0);

    // layer 0: din=400, H=1152
    gemm_xw_kernel<<<dim3(36, 256), 256>>>(act0, Wih0, bih0, bhh0, xw, 4 * HID_D, EMB_D);
    reset_bar_kernel<<<1, 1>>>();
    lstm_rec_kernel<HID_D, 8><<<144, 256, SMEM_BIG>>>(xw, Whh0, act1, 144);

    // layer 1: din=1152, H=1152
    gemm_xw_kernel<<<dim3(36, 256), 256>>>(act1, Wih1, bih1, bhh1, xw, 4 * HID_D, HID_D);
    reset_bar_kernel<<<1, 1>>>();
    lstm_rec_kernel<HID_D, 8><<<144, 256, SMEM_BIG>>>(xw, Whh1, act0, 144);

    // layer 2: din=1152, H=400
    gemm_xw_kernel<<<dim3(13, 256), 256>>>(act0, Wih2, bih2, bhh2, xw, 4 * EMB_D, HID_D);
    reset_bar_kernel<<<1, 1>>>();
    lstm_rec_kernel<EMB_D, 4><<<100, 256, SMEM_SMALL>>>(xw, Whh2, out, 100);
}